// round 1
// baseline (speedup 1.0000x reference)
#include <cuda_runtime.h>
#include <cuda_bf16.h>

// Problem shape (fixed by the dataset)
#define B_DIM 16
#define S_DIM 2048
#define D_DIM 256
#define ROWS  (B_DIM * S_DIM)          // 32768
#define P_ASEM 0.6f
#define Q_ASEM 0.4f
#define MASK_FILL 1e-9f

// Scratch for projected scores (no cudaMalloc allowed)
__device__ float g_si[ROWS];  // si + bias folded in
__device__ float g_sj[ROWS];

// ---------------------------------------------------------------------------
// Kernel 1: per-row dual dot product.
//   si[b,s] = dot(x[b,s,:], W[0:256]) + bias
//   sj[b,s] = dot(x[b,s,:], W[256:512])
// One warp per row. x row = 256 floats = 64 float4; 32 lanes x 2 float4 each.
// ---------------------------------------------------------------------------
__global__ void proj_kernel(const float* __restrict__ x,
                            const float* __restrict__ W,
                            const float* __restrict__ bias) {
    const int warps_per_block = blockDim.x >> 5;
    const int row = blockIdx.x * warps_per_block + (threadIdx.x >> 5);
    const int lane = threadIdx.x & 31;
    if (row >= ROWS) return;

    const float4* x4  = reinterpret_cast<const float4*>(x) + (long)row * (D_DIM / 4);
    const float4* Wi4 = reinterpret_cast<const float4*>(W);            // W[0:256]
    const float4* Wj4 = reinterpret_cast<const float4*>(W + D_DIM);    // W[256:512]

    float si = 0.f, sj = 0.f;
#pragma unroll
    for (int t = 0; t < 2; ++t) {
        int k4 = lane + t * 32;        // 0..63
        float4 xv = x4[k4];
        float4 wi = Wi4[k4];
        float4 wj = Wj4[k4];
        si = fmaf(xv.x, wi.x, si); si = fmaf(xv.y, wi.y, si);
        si = fmaf(xv.z, wi.z, si); si = fmaf(xv.w, wi.w, si);
        sj = fmaf(xv.x, wj.x, sj); sj = fmaf(xv.y, wj.y, sj);
        sj = fmaf(xv.z, wj.z, sj); sj = fmaf(xv.w, wj.w, sj);
    }
#pragma unroll
    for (int off = 16; off > 0; off >>= 1) {
        si += __shfl_down_sync(0xFFFFFFFFu, si, off);
        sj += __shfl_down_sync(0xFFFFFFFFu, sj, off);
    }
    if (lane == 0) {
        g_si[row] = si + bias[0];
        g_sj[row] = sj;
    }
}

// ---------------------------------------------------------------------------
// Kernel 2: fused elementwise over the [B,S,S] output, float4 per thread.
//   out = (mi & mj) ? P*sigmoid(si+sj) + Q*adj : 1e-9
// ---------------------------------------------------------------------------
__global__ void fuse_kernel(const float4* __restrict__ adj4,
                            const int*    __restrict__ mask,
                            float4*       __restrict__ out4) {
    const unsigned idx = blockIdx.x * blockDim.x + threadIdx.x; // float4 index
    // total float4 elems = 16 * 2048 * 512 = 16,777,216 ; all powers of two
    const unsigned jt  = idx & 511u;           // j / 4
    const unsigned i   = (idx >> 9) & 2047u;   // row within batch
    const unsigned b   = idx >> 20;            // batch
    const unsigned row = (b << 11) + i;

    const float si = g_si[row];
    const int   mi = mask[row];

    const float4 sj = reinterpret_cast<const float4*>(g_sj)[(b << 9) + jt];
    const int4   mj = reinterpret_cast<const int4*>(mask)[(b << 9) + jt];
    const float4 a  = adj4[idx];

    float4 r;
    {
        float z = si + sj.x;
        float s = __fdividef(1.f, 1.f + __expf(-z));
        r.x = (mi & mj.x) ? fmaf(P_ASEM, s, Q_ASEM * a.x) : MASK_FILL;
    }
    {
        float z = si + sj.y;
        float s = __fdividef(1.f, 1.f + __expf(-z));
        r.y = (mi & mj.y) ? fmaf(P_ASEM, s, Q_ASEM * a.y) : MASK_FILL;
    }
    {
        float z = si + sj.z;
        float s = __fdividef(1.f, 1.f + __expf(-z));
        r.z = (mi & mj.z) ? fmaf(P_ASEM, s, Q_ASEM * a.z) : MASK_FILL;
    }
    {
        float z = si + sj.w;
        float s = __fdividef(1.f, 1.f + __expf(-z));
        r.w = (mi & mj.w) ? fmaf(P_ASEM, s, Q_ASEM * a.w) : MASK_FILL;
    }
    out4[idx] = r;
}

// ---------------------------------------------------------------------------
// Launch
// Inputs (metadata order): 0:x [16,2048,256] f32, 1:adj [16,2048,2048] f32,
//                          2:mask [16,2048] i32, 3:W [1,512] f32, 4:b [1] f32
// Output: [16,2048,2048] f32
// ---------------------------------------------------------------------------
extern "C" void kernel_launch(void* const* d_in, const int* in_sizes, int n_in,
                              void* d_out, int out_size) {
    const float* x    = (const float*)d_in[0];
    const float* adj  = (const float*)d_in[1];
    const int*   mask = (const int*)d_in[2];
    const float* W    = (const float*)d_in[3];
    const float* bias = (const float*)d_in[4];
    float* out = (float*)d_out;

    // Kernel 1: 32768 rows, 8 warps (8 rows) per block of 256 threads
    proj_kernel<<<ROWS / 8, 256>>>(x, W, bias);

    // Kernel 2: 16.78M float4 threads
    const unsigned total4 = (unsigned)B_DIM * S_DIM * (S_DIM / 4);
    fuse_kernel<<<total4 / 256, 256>>>(reinterpret_cast<const float4*>(adj),
                                       mask,
                                       reinterpret_cast<float4*>(out));
}

// round 2
// speedup vs baseline: 1.0773x; 1.0773x over previous
#include <cuda_runtime.h>
#include <cuda_bf16.h>

// Problem shape (fixed by the dataset)
#define B_DIM 16
#define S_DIM 2048
#define D_DIM 256
#define ROWS  (B_DIM * S_DIM)          // 32768
#define P_ASEM 0.6f
#define Q_ASEM 0.4f
#define MASK_FILL 1e-9f

// Scratch for projected scores (no cudaMalloc allowed)
__device__ float g_si[ROWS];  // si + bias folded in
__device__ float g_sj[ROWS];

// ---------------------------------------------------------------------------
// Kernel 1: per-row dual dot product (warp per row).
//   si[b,s] = dot(x[b,s,:], W[0:256]) + bias ;  sj[b,s] = dot(x[b,s,:], W[256:512])
// ---------------------------------------------------------------------------
__global__ void proj_kernel(const float* __restrict__ x,
                            const float* __restrict__ W,
                            const float* __restrict__ bias) {
    const int row  = blockIdx.x * (blockDim.x >> 5) + (threadIdx.x >> 5);
    const int lane = threadIdx.x & 31;

    const float4* x4  = reinterpret_cast<const float4*>(x) + (long)row * (D_DIM / 4);
    const float4* Wi4 = reinterpret_cast<const float4*>(W);            // W[0:256]
    const float4* Wj4 = reinterpret_cast<const float4*>(W + D_DIM);    // W[256:512]

    // batch the loads up front (MLP)
    float4 xv0 = x4[lane];
    float4 xv1 = x4[lane + 32];
    float4 wi0 = __ldg(&Wi4[lane]);
    float4 wi1 = __ldg(&Wi4[lane + 32]);
    float4 wj0 = __ldg(&Wj4[lane]);
    float4 wj1 = __ldg(&Wj4[lane + 32]);

    float si = 0.f, sj = 0.f;
    si = fmaf(xv0.x, wi0.x, si); si = fmaf(xv0.y, wi0.y, si);
    si = fmaf(xv0.z, wi0.z, si); si = fmaf(xv0.w, wi0.w, si);
    si = fmaf(xv1.x, wi1.x, si); si = fmaf(xv1.y, wi1.y, si);
    si = fmaf(xv1.z, wi1.z, si); si = fmaf(xv1.w, wi1.w, si);
    sj = fmaf(xv0.x, wj0.x, sj); sj = fmaf(xv0.y, wj0.y, sj);
    sj = fmaf(xv0.z, wj0.z, sj); sj = fmaf(xv0.w, wj0.w, sj);
    sj = fmaf(xv1.x, wj1.x, sj); sj = fmaf(xv1.y, wj1.y, sj);
    sj = fmaf(xv1.z, wj1.z, sj); sj = fmaf(xv1.w, wj1.w, sj);

#pragma unroll
    for (int off = 16; off > 0; off >>= 1) {
        si += __shfl_down_sync(0xFFFFFFFFu, si, off);
        sj += __shfl_down_sync(0xFFFFFFFFu, sj, off);
    }
    if (lane == 0) {
        g_si[row] = si + __ldg(bias);
        g_sj[row] = sj;
    }
}

// ---------------------------------------------------------------------------
// Kernel 2: fused elementwise, 4 float4 per thread (MLP=4), streaming hints.
// Block handles a contiguous chunk of 1024 float4 (= 2 output rows);
// thread t touches chunk[t], [t+256], [t+512], [t+768] — coalesced groups.
// ---------------------------------------------------------------------------
__device__ __forceinline__ float sig_blend(float si, float sjv, int m, float a) {
    float z = si + sjv;
    float s = __fdividef(1.f, 1.f + __expf(-z));
    return m ? fmaf(P_ASEM, s, Q_ASEM * a) : MASK_FILL;
}

__global__ __launch_bounds__(256) void fuse_kernel(const float4* __restrict__ adj4,
                                                   const int*    __restrict__ mask,
                                                   float4*       __restrict__ out4) {
    const unsigned base = (blockIdx.x << 10) + threadIdx.x;  // float4 index of elem 0

    // ---- issue all 4 adj streaming loads up front ----
    float4 a0 = __ldcs(&adj4[base]);
    float4 a1 = __ldcs(&adj4[base + 256]);
    float4 a2 = __ldcs(&adj4[base + 512]);
    float4 a3 = __ldcs(&adj4[base + 768]);

    const unsigned idx0 = base, idx1 = base + 256, idx2 = base + 512, idx3 = base + 768;

    const unsigned row0 = idx0 >> 9, row1 = idx1 >> 9, row2 = idx2 >> 9, row3 = idx3 >> 9;
    const unsigned c0 = ((row0 >> 11) << 9) + (idx0 & 511u);
    const unsigned c1 = ((row1 >> 11) << 9) + (idx1 & 511u);
    const unsigned c2 = ((row2 >> 11) << 9) + (idx2 & 511u);
    const unsigned c3 = ((row3 >> 11) << 9) + (idx3 & 511u);

    const float4* sj4 = reinterpret_cast<const float4*>(g_sj);
    const int4*   mj4 = reinterpret_cast<const int4*>(mask);

    float4 sj0 = __ldg(&sj4[c0]);
    float4 sj1 = __ldg(&sj4[c1]);
    float4 sj2 = __ldg(&sj4[c2]);
    float4 sj3 = __ldg(&sj4[c3]);
    int4   m0  = __ldg(&mj4[c0]);
    int4   m1  = __ldg(&mj4[c1]);
    int4   m2  = __ldg(&mj4[c2]);
    int4   m3  = __ldg(&mj4[c3]);

    float si0 = g_si[row0];  int mi0 = mask[row0];
    float si1 = g_si[row1];  int mi1 = mask[row1];
    float si2 = g_si[row2];  int mi2 = mask[row2];
    float si3 = g_si[row3];  int mi3 = mask[row3];

    float4 r;
    r.x = sig_blend(si0, sj0.x, mi0 & m0.x, a0.x);
    r.y = sig_blend(si0, sj0.y, mi0 & m0.y, a0.y);
    r.z = sig_blend(si0, sj0.z, mi0 & m0.z, a0.z);
    r.w = sig_blend(si0, sj0.w, mi0 & m0.w, a0.w);
    __stcs(&out4[idx0], r);

    r.x = sig_blend(si1, sj1.x, mi1 & m1.x, a1.x);
    r.y = sig_blend(si1, sj1.y, mi1 & m1.y, a1.y);
    r.z = sig_blend(si1, sj1.z, mi1 & m1.z, a1.z);
    r.w = sig_blend(si1, sj1.w, mi1 & m1.w, a1.w);
    __stcs(&out4[idx1], r);

    r.x = sig_blend(si2, sj2.x, mi2 & m2.x, a2.x);
    r.y = sig_blend(si2, sj2.y, mi2 & m2.y, a2.y);
    r.z = sig_blend(si2, sj2.z, mi2 & m2.z, a2.z);
    r.w = sig_blend(si2, sj2.w, mi2 & m2.w, a2.w);
    __stcs(&out4[idx2], r);

    r.x = sig_blend(si3, sj3.x, mi3 & m3.x, a3.x);
    r.y = sig_blend(si3, sj3.y, mi3 & m3.y, a3.y);
    r.z = sig_blend(si3, sj3.z, mi3 & m3.z, a3.z);
    r.w = sig_blend(si3, sj3.w, mi3 & m3.w, a3.w);
    __stcs(&out4[idx3], r);
}

// ---------------------------------------------------------------------------
// Launch
// Inputs (metadata order): 0:x [16,2048,256] f32, 1:adj [16,2048,2048] f32,
//                          2:mask [16,2048] i32, 3:W [1,512] f32, 4:b [1] f32
// Output: [16,2048,2048] f32
// ---------------------------------------------------------------------------
extern "C" void kernel_launch(void* const* d_in, const int* in_sizes, int n_in,
                              void* d_out, int out_size) {
    const float* x    = (const float*)d_in[0];
    const float* adj  = (const float*)d_in[1];
    const int*   mask = (const int*)d_in[2];
    const float* W    = (const float*)d_in[3];
    const float* bias = (const float*)d_in[4];
    float* out = (float*)d_out;

    // Kernel 1: 32768 rows, 8 warps (8 rows) per block of 256 threads
    proj_kernel<<<ROWS / 8, 256>>>(x, W, bias);

    // Kernel 2: 16,777,216 float4 total / 1024 per block = 16384 blocks
    fuse_kernel<<<16384, 256>>>(reinterpret_cast<const float4*>(adj),
                                mask,
                                reinterpret_cast<float4*>(out));
}

// round 3
// speedup vs baseline: 1.3289x; 1.2336x over previous
#include <cuda_runtime.h>
#include <cuda_bf16.h>

// Problem shape (fixed by the dataset)
#define B_DIM 16
#define S_DIM 2048
#define D_DIM 256
#define ROWS  (B_DIM * S_DIM)          // 32768
#define P_ASEM 0.6f
#define Q_ASEM 0.4f
#define MASK_FILL 1e-9f

// Scratch for projected scores (no cudaMalloc allowed)
__device__ float g_si[ROWS];  // si + bias folded in
__device__ float g_sj[ROWS];

// ---------------------------------------------------------------------------
// Kernel 1: per-row dual dot product (warp per row).
//   si[b,s] = dot(x[b,s,:], W[0:256]) + bias ;  sj[b,s] = dot(x[b,s,:], W[256:512])
// ---------------------------------------------------------------------------
__global__ void proj_kernel(const float* __restrict__ x,
                            const float* __restrict__ W,
                            const float* __restrict__ bias) {
    const int row  = blockIdx.x * (blockDim.x >> 5) + (threadIdx.x >> 5);
    const int lane = threadIdx.x & 31;

    const float4* x4  = reinterpret_cast<const float4*>(x) + (long)row * (D_DIM / 4);
    const float4* Wi4 = reinterpret_cast<const float4*>(W);            // W[0:256]
    const float4* Wj4 = reinterpret_cast<const float4*>(W + D_DIM);    // W[256:512]

    float4 xv0 = x4[lane];
    float4 xv1 = x4[lane + 32];
    float4 wi0 = __ldg(&Wi4[lane]);
    float4 wi1 = __ldg(&Wi4[lane + 32]);
    float4 wj0 = __ldg(&Wj4[lane]);
    float4 wj1 = __ldg(&Wj4[lane + 32]);

    float si = 0.f, sj = 0.f;
    si = fmaf(xv0.x, wi0.x, si); si = fmaf(xv0.y, wi0.y, si);
    si = fmaf(xv0.z, wi0.z, si); si = fmaf(xv0.w, wi0.w, si);
    si = fmaf(xv1.x, wi1.x, si); si = fmaf(xv1.y, wi1.y, si);
    si = fmaf(xv1.z, wi1.z, si); si = fmaf(xv1.w, wi1.w, si);
    sj = fmaf(xv0.x, wj0.x, sj); sj = fmaf(xv0.y, wj0.y, sj);
    sj = fmaf(xv0.z, wj0.z, sj); sj = fmaf(xv0.w, wj0.w, sj);
    sj = fmaf(xv1.x, wj1.x, sj); sj = fmaf(xv1.y, wj1.y, sj);
    sj = fmaf(xv1.z, wj1.z, sj); sj = fmaf(xv1.w, wj1.w, sj);

#pragma unroll
    for (int off = 16; off > 0; off >>= 1) {
        si += __shfl_down_sync(0xFFFFFFFFu, si, off);
        sj += __shfl_down_sync(0xFFFFFFFFu, sj, off);
    }
    if (lane == 0) {
        g_si[row] = si + __ldg(bias);
        g_sj[row] = sj;
    }
}

// ---------------------------------------------------------------------------
// Kernel 2: fused elementwise with masked-row adj-skip.
// Block = 256 threads, covers exactly 2 output rows (1024 float4).
//   row masked   -> pure fill store, NO adj read (saves ~50% of read stream)
//   row unmasked -> stream adj, sigmoid-blend, store
// The mi branch is uniform across the whole block (rows map 1:1 to halves).
// ---------------------------------------------------------------------------
__device__ __forceinline__ float sig_blend(float si, float sjv, int m, float a) {
    float z = si + sjv;
    float s = __fdividef(1.f, 1.f + __expf(-z));
    return m ? fmaf(P_ASEM, s, Q_ASEM * a) : MASK_FILL;
}

__global__ __launch_bounds__(256) void fuse_kernel(const float4* __restrict__ adj4,
                                                   const int*    __restrict__ mask,
                                                   float4*       __restrict__ out4) {
    const unsigned tid       = threadIdx.x;
    const unsigned blockBase = blockIdx.x << 10;        // first float4 of the block
    const unsigned row0      = blockIdx.x << 1;         // first global row
    const unsigned cbase     = ((row0 >> 11) << 9) + tid; // sj/mask float4 col base

    const float4* sj4 = reinterpret_cast<const float4*>(g_sj);
    const int4*   mj4 = reinterpret_cast<const int4*>(mask);

#pragma unroll
    for (int r = 0; r < 2; ++r) {
        const unsigned row = row0 + r;
        const unsigned o0  = blockBase + (r << 9) + tid;   // chunk A float4 idx
        const unsigned o1  = o0 + 256;                     // chunk B
        const int mi = mask[row];

        if (mi) {
            // stream the two adj chunks (read-once)
            float4 a0 = __ldcs(&adj4[o0]);
            float4 a1 = __ldcs(&adj4[o1]);
            const float si = g_si[row];

            float4 sjA = __ldg(&sj4[cbase]);
            float4 sjB = __ldg(&sj4[cbase + 256]);
            int4   mA  = __ldg(&mj4[cbase]);
            int4   mB  = __ldg(&mj4[cbase + 256]);

            float4 out;
            out.x = sig_blend(si, sjA.x, mA.x, a0.x);
            out.y = sig_blend(si, sjA.y, mA.y, a0.y);
            out.z = sig_blend(si, sjA.z, mA.z, a0.z);
            out.w = sig_blend(si, sjA.w, mA.w, a0.w);
            __stcs(&out4[o0], out);

            out.x = sig_blend(si, sjB.x, mB.x, a1.x);
            out.y = sig_blend(si, sjB.y, mB.y, a1.y);
            out.z = sig_blend(si, sjB.z, mB.z, a1.z);
            out.w = sig_blend(si, sjB.w, mB.w, a1.w);
            __stcs(&out4[o1], out);
        } else {
            // whole row is MASK_FILL; no adj traffic at all
            const float4 fill = make_float4(MASK_FILL, MASK_FILL, MASK_FILL, MASK_FILL);
            __stcs(&out4[o0], fill);
            __stcs(&out4[o1], fill);
        }
    }
}

// ---------------------------------------------------------------------------
// Launch
// Inputs (metadata order): 0:x [16,2048,256] f32, 1:adj [16,2048,2048] f32,
//                          2:mask [16,2048] i32, 3:W [1,512] f32, 4:b [1] f32
// Output: [16,2048,2048] f32
// ---------------------------------------------------------------------------
extern "C" void kernel_launch(void* const* d_in, const int* in_sizes, int n_in,
                              void* d_out, int out_size) {
    const float* x    = (const float*)d_in[0];
    const float* adj  = (const float*)d_in[1];
    const int*   mask = (const int*)d_in[2];
    const float* W    = (const float*)d_in[3];
    const float* bias = (const float*)d_in[4];
    float* out = (float*)d_out;

    // Kernel 1: 32768 rows, 8 warps (8 rows) per block of 256 threads
    proj_kernel<<<ROWS / 8, 256>>>(x, W, bias);

    // Kernel 2: one block per 2 output rows -> 16384 blocks
    fuse_kernel<<<16384, 256>>>(reinterpret_cast<const float4*>(adj),
                                mask,
                                reinterpret_cast<float4*>(out));
}

// round 4
// speedup vs baseline: 1.3584x; 1.0222x over previous
#include <cuda_runtime.h>
#include <cuda_bf16.h>

// Problem shape (fixed by the dataset)
#define B_DIM 16
#define S_DIM 2048
#define D_DIM 256
#define ROWS  (B_DIM * S_DIM)          // 32768
#define P_ASEM 0.6f
#define Q_ASEM 0.4f
#define MASK_FILL 1e-9f

// Scratch for projected scores (no cudaMalloc allowed)
__device__ float g_si[ROWS];  // si + bias folded in
__device__ float g_sj[ROWS];

// ---------------------------------------------------------------------------
// Kernel 1: per-row dual dot product (warp per row).
// ---------------------------------------------------------------------------
__global__ void proj_kernel(const float* __restrict__ x,
                            const float* __restrict__ W,
                            const float* __restrict__ bias) {
    const int row  = blockIdx.x * (blockDim.x >> 5) + (threadIdx.x >> 5);
    const int lane = threadIdx.x & 31;

    const float4* x4  = reinterpret_cast<const float4*>(x) + (long)row * (D_DIM / 4);
    const float4* Wi4 = reinterpret_cast<const float4*>(W);            // W[0:256]
    const float4* Wj4 = reinterpret_cast<const float4*>(W + D_DIM);    // W[256:512]

    float4 xv0 = x4[lane];
    float4 xv1 = x4[lane + 32];
    float4 wi0 = __ldg(&Wi4[lane]);
    float4 wi1 = __ldg(&Wi4[lane + 32]);
    float4 wj0 = __ldg(&Wj4[lane]);
    float4 wj1 = __ldg(&Wj4[lane + 32]);

    float si = 0.f, sj = 0.f;
    si = fmaf(xv0.x, wi0.x, si); si = fmaf(xv0.y, wi0.y, si);
    si = fmaf(xv0.z, wi0.z, si); si = fmaf(xv0.w, wi0.w, si);
    si = fmaf(xv1.x, wi1.x, si); si = fmaf(xv1.y, wi1.y, si);
    si = fmaf(xv1.z, wi1.z, si); si = fmaf(xv1.w, wi1.w, si);
    sj = fmaf(xv0.x, wj0.x, sj); sj = fmaf(xv0.y, wj0.y, sj);
    sj = fmaf(xv0.z, wj0.z, sj); sj = fmaf(xv0.w, wj0.w, sj);
    sj = fmaf(xv1.x, wj1.x, sj); sj = fmaf(xv1.y, wj1.y, sj);
    sj = fmaf(xv1.z, wj1.z, sj); sj = fmaf(xv1.w, wj1.w, sj);

#pragma unroll
    for (int off = 16; off > 0; off >>= 1) {
        si += __shfl_down_sync(0xFFFFFFFFu, si, off);
        sj += __shfl_down_sync(0xFFFFFFFFu, sj, off);
    }
    if (lane == 0) {
        g_si[row] = si + __ldg(bias);
        g_sj[row] = sj;
    }
}

// ---------------------------------------------------------------------------
// Kernel 2: fused elementwise, 4 rows per block (all in the same batch, so the
// sj/mask column vectors are shared across rows and loaded ONCE). All adj
// loads for unmasked rows are issued up front (MLP up to 8 LDG.128/thread);
// masked rows write pure fill with zero read traffic.
// ---------------------------------------------------------------------------
#define RPB 4   // rows per block

__device__ __forceinline__ float sig_blend(float si, float sjv, int m, float a) {
    float z = si + sjv;
    float s = __fdividef(1.f, 1.f + __expf(-z));
    return m ? fmaf(P_ASEM, s, Q_ASEM * a) : MASK_FILL;
}

__global__ __launch_bounds__(256) void fuse_kernel(const float4* __restrict__ adj4,
                                                   const int*    __restrict__ mask,
                                                   float4*       __restrict__ out4) {
    const unsigned tid   = threadIdx.x;
    const unsigned row0  = blockIdx.x * RPB;                 // rows row0..row0+3 (same batch)
    const unsigned base  = row0 << 9;                        // first float4 of the block
    const unsigned cbase = ((row0 >> 11) << 9) + tid;        // sj/mask col float4 index

    // per-row masks (uniform across block for each row)
    int mi[RPB];
#pragma unroll
    for (int r = 0; r < RPB; ++r) mi[r] = mask[row0 + r];

    // issue ALL adj loads for unmasked rows up front (predicated, independent)
    float4 aA[RPB], aB[RPB];
#pragma unroll
    for (int r = 0; r < RPB; ++r) {
        if (mi[r]) {
            const unsigned o = base + (r << 9) + tid;
            aA[r] = __ldcs(&adj4[o]);
            aB[r] = __ldcs(&adj4[o + 256]);
        }
    }

    // column vectors: shared by all RPB rows, loaded once
    const float4* sj4 = reinterpret_cast<const float4*>(g_sj);
    const int4*   mj4 = reinterpret_cast<const int4*>(mask);
    const float4 sjA = __ldg(&sj4[cbase]);
    const float4 sjB = __ldg(&sj4[cbase + 256]);
    const int4   mA  = __ldg(&mj4[cbase]);
    const int4   mB  = __ldg(&mj4[cbase + 256]);

#pragma unroll
    for (int r = 0; r < RPB; ++r) {
        const unsigned o = base + (r << 9) + tid;
        if (mi[r]) {
            const float si = g_si[row0 + r];
            float4 out;
            out.x = sig_blend(si, sjA.x, mA.x, aA[r].x);
            out.y = sig_blend(si, sjA.y, mA.y, aA[r].y);
            out.z = sig_blend(si, sjA.z, mA.z, aA[r].z);
            out.w = sig_blend(si, sjA.w, mA.w, aA[r].w);
            __stcs(&out4[o], out);

            out.x = sig_blend(si, sjB.x, mB.x, aB[r].x);
            out.y = sig_blend(si, sjB.y, mB.y, aB[r].y);
            out.z = sig_blend(si, sjB.z, mB.z, aB[r].z);
            out.w = sig_blend(si, sjB.w, mB.w, aB[r].w);
            __stcs(&out4[o + 256], out);
        } else {
            const float4 fill = make_float4(MASK_FILL, MASK_FILL, MASK_FILL, MASK_FILL);
            __stcs(&out4[o], fill);
            __stcs(&out4[o + 256], fill);
        }
    }
}

// ---------------------------------------------------------------------------
// Launch
// Inputs (metadata order): 0:x [16,2048,256] f32, 1:adj [16,2048,2048] f32,
//                          2:mask [16,2048] i32, 3:W [1,512] f32, 4:b [1] f32
// Output: [16,2048,2048] f32
// ---------------------------------------------------------------------------
extern "C" void kernel_launch(void* const* d_in, const int* in_sizes, int n_in,
                              void* d_out, int out_size) {
    const float* x    = (const float*)d_in[0];
    const float* adj  = (const float*)d_in[1];
    const int*   mask = (const int*)d_in[2];
    const float* W    = (const float*)d_in[3];
    const float* bias = (const float*)d_in[4];
    float* out = (float*)d_out;

    // Kernel 1: 32768 rows, 8 warps (8 rows) per block of 256 threads
    proj_kernel<<<ROWS / 8, 256>>>(x, W, bias);

    // Kernel 2: one block per 4 output rows -> 8192 blocks
    fuse_kernel<<<ROWS / RPB, 256>>>(reinterpret_cast<const float4*>(adj),
                                     mask,
                                     reinterpret_cast<float4*>(out));
}